// round 15
// baseline (speedup 1.0000x reference)
#include <cuda_runtime.h>
#include <cuda_fp16.h>
#include <cstdint>

// Problem constants
#define BATCH   2
#define SEQ     2048
#define DMODEL  2048
#define NHEADS  16
#define DHEAD   128

#define KC2  64                    // K elems per GEMM chunk
#define NCH2 32                    // chunks (K = 2048)
#define SCALE 0.08838834764831845f // 1/sqrt(128)

// ---------------------------------------------------------------------------
// Scratch (alloc-free: __device__ globals)
// ---------------------------------------------------------------------------
__device__ __align__(128) uint32_t g_xf [(size_t)32 * NCH2 * 4096];  // x     [4096,2048]
__device__ __align__(128) uint32_t g_of [(size_t)32 * NCH2 * 4096];  // attn out
__device__ __align__(128) uint32_t g_wqf[(size_t)48 * NCH2 * 4096];  // W_qkv [6144,2048]
__device__ __align__(128) uint32_t g_wof[(size_t)16 * NCH2 * 4096];  // W_out [2048,2048]

__device__ __align__(128) uint32_t g_Qf[(size_t)32 * 32 * 4096];     // pre-scaled by 1/sqrt(dh)
__device__ __align__(128) uint32_t g_Kf[(size_t)32 * 32 * 4096];
__device__ __align__(128) uint32_t g_Vf[(size_t)32 * 32 * 4096];

__device__ __forceinline__ uint32_t pack_h2(float lo, float hi) {
    __half2 h = __floats2half2_rn(lo, hi);
    return *reinterpret_cast<uint32_t*>(&h);
}

__device__ __forceinline__ void mma_f16(float* d, const uint32_t* a, const uint32_t* b) {
    asm volatile(
        "mma.sync.aligned.m16n8k16.row.col.f32.f16.f16.f32 "
        "{%0,%1,%2,%3}, {%4,%5,%6,%7}, {%8,%9}, {%0,%1,%2,%3};"
        : "+f"(d[0]), "+f"(d[1]), "+f"(d[2]), "+f"(d[3])
        : "r"(a[0]), "r"(a[1]), "r"(a[2]), "r"(a[3]), "r"(b[0]), "r"(b[1]));
}

__device__ __forceinline__ void cpa16(uint32_t dst, const void* src) {
    asm volatile("cp.async.cg.shared.global [%0], [%1], 16;"
                 :: "r"(dst), "l"(src) : "memory");
}
#define CPA_COMMIT() asm volatile("cp.async.commit_group;" ::: "memory")
#define CPA_WAIT(n)  asm volatile("cp.async.wait_group %0;" :: "n"(n) : "memory")

__device__ __forceinline__ uint32_t smem_u32(const void* p) {
    uint32_t a;
    asm("{ .reg .u64 t; cvta.to.shared.u64 t, %1; cvt.u32.u64 %0, t; }"
        : "=r"(a) : "l"(p));
    return a;
}

// Fragment index helpers (element (s,d) of head-batch bh)
__device__ __forceinline__ size_t qf_u32(int bh, int s, int d) {
    return (size_t)((bh * 32 + (s >> 6)) * 32 + (d >> 4) * 4 + ((s >> 4) & 3)) * 128
         + (((s & 7) * 4 + ((d & 7) >> 1)) << 2) + (((d >> 3) & 1) << 1) + ((s >> 3) & 1);
}
__device__ __forceinline__ size_t kf_u32(int bh, int s, int d) {
    return (size_t)((bh * 32 + (s >> 6)) * 64 + (d >> 4) * 8 + ((s >> 3) & 7)) * 64
         + (((s & 7) * 4 + ((d & 7) >> 1)) << 1) + ((d >> 3) & 1);
}
__device__ __forceinline__ size_t vf_u16(int bh, int s, int d) {
    return ((size_t)((bh * 32 + (s >> 6)) * 64 + (d >> 3) * 4 + ((s >> 4) & 3)) * 64
         + (((d & 7) * 4 + ((s & 7) >> 1)) << 1) + ((s >> 3) & 1)) * 2 + (s & 1);
}

// ---------------------------------------------------------------------------
// Fused conversion kernel: fp32 row-major -> fp16 fragment layouts.
// ---------------------------------------------------------------------------
__device__ __forceinline__ void conv_A_body(
    const float* __restrict__ src, uint32_t* __restrict__ dst,
    int ch, int mb, int tid, float (*s)[65])
{
    const float* base = src + (size_t)mb * 128 * DMODEL + ch * KC2;
#pragma unroll
    for (int i = 0; i < 8; i++) {
        const int idx = tid + i * 256;
        const int row = idx >> 4, c4 = idx & 15;
        float4 v = *(const float4*)(base + (size_t)row * DMODEL + c4 * 4);
        s[row][c4 * 4 + 0] = v.x; s[row][c4 * 4 + 1] = v.y;
        s[row][c4 * 4 + 2] = v.z; s[row][c4 * 4 + 3] = v.w;
    }
    __syncthreads();
    uint32_t* out = dst + ((size_t)mb * NCH2 + ch) * 4096;
#pragma unroll
    for (int i = 0; i < 16; i++) {
        const int u = tid + i * 256;
        const int blk = u >> 7, rem = u & 127;
        const int lane = rem >> 2, reg = rem & 3;
        const int gm = blk >> 2, ks = blk & 3;
        const int r = (reg & 1) * 8 + (lane >> 2);
        const int c = (reg >> 1) * 8 + (lane & 3) * 2;
        const int k = ks * 16 + c;
        out[u] = pack_h2(s[gm * 16 + r][k], s[gm * 16 + r][k + 1]);
    }
}

__device__ __forceinline__ void conv_B_body(
    const float* __restrict__ src, uint32_t* __restrict__ dst,
    int ch, int nb, int tid, float (*s)[65])
{
    const float* base = src + (size_t)nb * 128 * DMODEL + ch * KC2;
#pragma unroll
    for (int i = 0; i < 8; i++) {
        const int idx = tid + i * 256;
        const int row = idx >> 4, c4 = idx & 15;
        float4 v = *(const float4*)(base + (size_t)row * DMODEL + c4 * 4);
        s[row][c4 * 4 + 0] = v.x; s[row][c4 * 4 + 1] = v.y;
        s[row][c4 * 4 + 2] = v.z; s[row][c4 * 4 + 3] = v.w;
    }
    __syncthreads();
    uint32_t* out = dst + ((size_t)nb * NCH2 + ch) * 4096;
#pragma unroll
    for (int i = 0; i < 16; i++) {
        const int u = tid + i * 256;
        const int blk = u >> 6, rem = u & 63;
        const int lane = rem >> 1, reg = rem & 1;
        const int gn = blk >> 2, ks = blk & 3;
        const int n = lane >> 2, tig = lane & 3;
        const int k = ks * 16 + reg * 8 + tig * 2;
        out[u] = pack_h2(s[gn * 8 + n][k], s[gn * 8 + n][k + 1]);
    }
}

__global__ void __launch_bounds__(256)
conv_all(const float* __restrict__ x, const float* __restrict__ wq,
         const float* __restrict__ wo)
{
    __shared__ float s[128][65];
    const int bid = blockIdx.x;
    const int tid = threadIdx.x;
    if (bid < 1024) {
        conv_A_body(x,  g_xf,  bid & 31, bid >> 5, tid, s);
    } else if (bid < 2560) {
        const int b2 = bid - 1024;
        conv_B_body(wq, g_wqf, b2 & 31, b2 >> 5, tid, s);
    } else {
        const int b2 = bid - 2560;
        conv_B_body(wo, g_wof, b2 & 31, b2 >> 5, tid, s);
    }
}

// ---------------------------------------------------------------------------
// QKV GEMM (round-12): 128-thread CTAs, tile 128x96, 3-stage ring,
// ONE barrier per chunk. Epilogue emits Q/K/V fp16 fragments, Q pre-scaled.
// ---------------------------------------------------------------------------
#define QSTG     7168
#define QKV_SMEM (3 * QSTG * 4)             // 86016 bytes

__global__ void __launch_bounds__(128)
gemm_qkv(const uint32_t* __restrict__ Af, const uint32_t* __restrict__ Bf)
{
    extern __shared__ uint32_t us[];
    const int tid = threadIdx.x;
    const int wid = tid >> 5;
    const int lid = tid & 31;
    const int wm  = wid & 1;
    const int wn  = wid >> 1;
    const int mb  = blockIdx.y;
    const int n0  = blockIdx.x * 96;
    const uint32_t sb = smem_u32(us);

    float acc[4][6][4];
#pragma unroll
    for (int i = 0; i < 4; i++)
#pragma unroll
        for (int j = 0; j < 6; j++)
#pragma unroll
            for (int v = 0; v < 4; v++) acc[i][j][v] = 0.0f;

    auto issue = [&](int c, int st) {
        const uint32_t sA = sb + st * (QSTG * 4);
        const uint32_t sB = sA + 16384;
        const uint32_t* gA = Af + ((size_t)mb * NCH2 + c) * 4096;
#pragma unroll
        for (int i = 0; i < 8; i++) {
            const int o = tid + i * 128;
            cpa16(sA + o * 16, gA + (size_t)o * 4);
        }
#pragma unroll
        for (int i = 0; i < 6; i++) {
            const int idx = tid + i * 128;
            const int g   = idx >> 6;
            const int w64 = idx & 63;
            const int col = n0 + g * 8;
            const uint32_t* gB = Bf + ((size_t)(col >> 7) * NCH2 + c) * 4096
                                    + ((col >> 3) & 15) * 256 + w64 * 4;
            cpa16(sB + (g * 256 + w64 * 4) * 4, gB);
        }
        CPA_COMMIT();
    };

    issue(0, 0);
    issue(1, 1);

    for (int c = 0; c < NCH2; ++c) {
        if (c < NCH2 - 1) { CPA_WAIT(1); }
        else              { CPA_WAIT(0); }
        __syncthreads();

        const uint32_t* uA = us + (c % 3) * QSTG;
        const uint32_t* uB = uA + 4096;
#pragma unroll
        for (int ks = 0; ks < 4; ks++) {
            uint4 a[4];
            uint32_t b[6][2];
#pragma unroll
            for (int mt = 0; mt < 4; mt++)
                a[mt] = *(const uint4*)&uA[(((wm * 4 + mt) * 4 + ks) * 32 + lid) * 4];
#pragma unroll
            for (int nt = 0; nt < 6; nt++) {
                const int g = wn * 6 + nt;
                *(uint2*)b[nt] = *(const uint2*)&uB[g * 256 + ks * 64 + lid * 2];
            }
#pragma unroll
            for (int mt = 0; mt < 4; mt++)
#pragma unroll
                for (int nt = 0; nt < 6; nt++)
                    mma_f16(acc[mt][nt], (const uint32_t*)&a[mt], b[nt]);
        }

        if (c + 2 < NCH2) issue(c + 2, (c + 2) % 3);
    }

    const int lr  = lid >> 2;
    const int lc2 = (lid & 3) * 2;
    const int m0  = mb * 128;
    __half* vh = (__half*)g_Vf;
#pragma unroll
    for (int mt = 0; mt < 4; mt++) {
        const int m = m0 + wm * 64 + mt * 16 + lr;
#pragma unroll
        for (int nt = 0; nt < 6; nt++) {
            const int cg = n0 + wn * 48 + nt * 8 + lc2;
            const int t  = cg >> 11;
            const int h  = (cg >> 7) & (NHEADS - 1);
            const int d  = cg & (DHEAD - 1);
            const int b  = m >> 11;
            const int s  = m & (SEQ - 1);
            const int bh = b * NHEADS + h;
            if (t == 0) {
                g_Qf[qf_u32(bh, s,     d)] = pack_h2(acc[mt][nt][0] * SCALE, acc[mt][nt][1] * SCALE);
                g_Qf[qf_u32(bh, s + 8, d)] = pack_h2(acc[mt][nt][2] * SCALE, acc[mt][nt][3] * SCALE);
            } else if (t == 1) {
                g_Kf[kf_u32(bh, s,     d)] = pack_h2(acc[mt][nt][0], acc[mt][nt][1]);
                g_Kf[kf_u32(bh, s + 8, d)] = pack_h2(acc[mt][nt][2], acc[mt][nt][3]);
            } else {
                vh[vf_u16(bh, s,     d    )] = __float2half_rn(acc[mt][nt][0]);
                vh[vf_u16(bh, s,     d + 1)] = __float2half_rn(acc[mt][nt][1]);
                vh[vf_u16(bh, s + 8, d    )] = __float2half_rn(acc[mt][nt][2]);
                vh[vf_u16(bh, s + 8, d + 1)] = __float2half_rn(acc[mt][nt][3]);
            }
        }
    }
}

// ---------------------------------------------------------------------------
// Output-projection GEMM (round-12): 128 threads, tile 128x128, 3-stage ring
// (96KB -> 2 CTAs/SM), ONE barrier per chunk (issue-after-compute).
// ---------------------------------------------------------------------------
#define OSTG     8192
#define OUT_SMEM (3 * OSTG * 4)             // 98304 bytes

__global__ void __launch_bounds__(128)
gemm_out(const uint32_t* __restrict__ Af, const uint32_t* __restrict__ Bf,
         float* __restrict__ C)
{
    extern __shared__ uint32_t us[];
    const int tid = threadIdx.x;
    const int wid = tid >> 5;
    const int lid = tid & 31;
    const int wm  = wid & 1;
    const int wn  = wid >> 1;
    const int mb  = blockIdx.y;
    const int nb  = blockIdx.x;
    const uint32_t sb = smem_u32(us);

    float acc[4][8][4];
#pragma unroll
    for (int i = 0; i < 4; i++)
#pragma unroll
        for (int j = 0; j < 8; j++)
#pragma unroll
            for (int v = 0; v < 4; v++) acc[i][j][v] = 0.0f;

    auto issue = [&](int c, int st) {
        const uint32_t sA = sb + st * (OSTG * 4);
        const uint32_t sB = sA + 16384;
        const uint32_t* gA = Af + ((size_t)mb * NCH2 + c) * 4096;
        const uint32_t* gB = Bf + ((size_t)nb * NCH2 + c) * 4096;
#pragma unroll
        for (int i = 0; i < 8; i++) {
            const int o = tid + i * 128;
            cpa16(sA + o * 16, gA + (size_t)o * 4);
        }
#pragma unroll
        for (int i = 0; i < 8; i++) {
            const int o = tid + i * 128;
            cpa16(sB + o * 16, gB + (size_t)o * 4);
        }
        CPA_COMMIT();
    };

    issue(0, 0);
    issue(1, 1);

    for (int c = 0; c < NCH2; ++c) {
        if (c < NCH2 - 1) { CPA_WAIT(1); }
        else              { CPA_WAIT(0); }
        __syncthreads();

        const uint32_t* uA = us + (c % 3) * OSTG;
        const uint32_t* uB = uA + 4096;
#pragma unroll
        for (int ks = 0; ks < 4; ks++) {
            uint4 a[4];
            uint32_t b[8][2];
#pragma unroll
            for (int mt = 0; mt < 4; mt++)
                a[mt] = *(const uint4*)&uA[(((wm * 4 + mt) * 4 + ks) * 32 + lid) * 4];
#pragma unroll
            for (int nt = 0; nt < 8; nt++) {
                const int gn = wn * 8 + nt;
                *(uint2*)b[nt] = *(const uint2*)&uB[(gn * 4 + ks) * 64 + lid * 2];
            }
#pragma unroll
            for (int mt = 0; mt < 4; mt++)
#pragma unroll
                for (int nt = 0; nt < 8; nt++)
                    mma_f16(acc[mt][nt], (const uint32_t*)&a[mt], b[nt]);
        }

        if (c + 2 < NCH2) issue(c + 2, (c + 2) % 3);
    }

    const int lr  = lid >> 2;
    const int lc2 = (lid & 3) * 2;
    const int m0  = mb * 128;
    const int n0  = nb * 128;
#pragma unroll
    for (int mt = 0; mt < 4; mt++) {
        const int m = m0 + wm * 64 + mt * 16 + lr;
#pragma unroll
        for (int nt = 0; nt < 8; nt++) {
            const int cg = n0 + wn * 64 + nt * 8 + lc2;
            float* dst = C + (size_t)m * DMODEL + cg;
            *(float2*)dst                         = make_float2(acc[mt][nt][0], acc[mt][nt][1]);
            *(float2*)(dst + (size_t)8 * DMODEL)  = make_float2(acc[mt][nt][2], acc[mt][nt][3]);
        }
    }
}

// ---------------------------------------------------------------------------
// Flash attention v8: 256 threads (8 warps), 128-row Q tiles, Q (pre-scaled)
// in registers, 64-col KV blocks in a 3-stage cp.async ring, ONE barrier per
// iteration. Halves KV gmem traffic and per-CTA overhead vs 64-row tiles.
// Epilogue writes out-proj A-fragments (g_of) directly.
// ---------------------------------------------------------------------------
#define KV_U32   4096
#define ATT_SMEM ((3 * 2 * KV_U32 + 8 * 576) * 4)  // 116736 bytes

__global__ void __launch_bounds__(256)
flash_attn_v8()
{
    extern __shared__ uint32_t sm32[];
    const int tid = threadIdx.x;
    const int wid = tid >> 5;                     // 0..7
    const int lid = tid & 31;
    const int qb  = gridDim.x - 1 - blockIdx.x;   // 128-row tile, big first
    const int bh  = blockIdx.y;
    const int b   = bh >> 4;
    const int h   = bh & (NHEADS - 1);
    uint32_t* Pw = sm32 + 3 * 2 * KV_U32 + wid * 576;
    const uint32_t sb = smem_u32(sm32);

    // ---- Q fragments into registers (two 64-row Qf tiles per CTA) ----
    uint32_t q[8][4];
    {
        const uint4* qg = (const uint4*)(g_Qf +
            (size_t)(bh * 32 + qb * 2 + (wid >> 2)) * 4096);
        const int bw = wid & 3;
#pragma unroll
        for (int kt = 0; kt < 8; kt++) {
            uint4 v = __ldg(&qg[(kt * 4 + bw) * 32 + lid]);
            q[kt][0] = v.x; q[kt][1] = v.y; q[kt][2] = v.z; q[kt][3] = v.w;
        }
    }

    auto issueKV = [&](int kb, int st) {
        const uint4* gk = (const uint4*)(g_Kf + (size_t)(bh * 32 + kb) * KV_U32);
        const uint4* gv = (const uint4*)(g_Vf + (size_t)(bh * 32 + kb) * KV_U32);
        const uint32_t base = sb + st * (2 * KV_U32 * 4);
#pragma unroll
        for (int i = 0; i < 4; i++)
            cpa16(base + (tid + i * 256) * 16, gk + tid + i * 256);
#pragma unroll
        for (int i = 0; i < 4; i++)
            cpa16(base + KV_U32 * 4 + (tid + i * 256) * 16, gv + tid + i * 256);
        CPA_COMMIT();
    };

    float o[16][4];
#pragma unroll
    for (int nt = 0; nt < 16; nt++)
#pragma unroll
        for (int v = 0; v < 4; v++) o[nt][v] = 0.0f;

    float mx0 = -1e30f, mx1 = -1e30f, l0 = 0.0f, l1 = 0.0f;
    const int lr = lid >> 2;
    const int lc = lid & 3;
    const int q0 = qb * 128;
    const int row0 = q0 + wid * 16 + lr;
    const int row1 = row0 + 8;

    const int nkb = 2 * qb + 2;                   // 64-col KV blocks needed
    issueKV(0, 0);
    if (nkb > 1) issueKV(1, 1);

    for (int kb = 0; kb < nkb; kb++) {
        if (kb + 1 < nkb) { CPA_WAIT(1); }
        else              { CPA_WAIT(0); }
        __syncthreads();

        const uint32_t* KB = sm32 + (kb % 3) * 2 * KV_U32;
        const uint32_t* VB = KB + KV_U32;

        float s[8][4];
#pragma unroll
        for (int nt = 0; nt < 8; nt++)
#pragma unroll
            for (int v = 0; v < 4; v++) s[nt][v] = 0.0f;

#pragma unroll
        for (int kt = 0; kt < 8; kt++)
#pragma unroll
            for (int nt = 0; nt < 8; nt++) {
                uint32_t bf[2];
                *(uint2*)bf = *(const uint2*)&KB[(kt * 8 + nt) * 64 + lid * 2];
                mma_f16(s[nt], q[kt], bf);
            }

        // Q pre-scaled; mask only the last two KV blocks (kb >= 2*qb)
        const bool domask = (kb >= 2 * qb);
        const int k0 = kb * 64;
        float ml0 = -1e30f, ml1 = -1e30f;
#pragma unroll
        for (int nt = 0; nt < 8; nt++) {
            const int c0 = k0 + nt * 8 + lc * 2;
            if (domask) {
                if (c0     > row0) s[nt][0] = -1e30f;
                if (c0 + 1 > row0) s[nt][1] = -1e30f;
                if (c0     > row1) s[nt][2] = -1e30f;
                if (c0 + 1 > row1) s[nt][3] = -1e30f;
            }
            ml0 = fmaxf(ml0, fmaxf(s[nt][0], s[nt][1]));
            ml1 = fmaxf(ml1, fmaxf(s[nt][2], s[nt][3]));
        }
        ml0 = fmaxf(ml0, __shfl_xor_sync(0xffffffffu, ml0, 1));
        ml0 = fmaxf(ml0, __shfl_xor_sync(0xffffffffu, ml0, 2));
        ml1 = fmaxf(ml1, __shfl_xor_sync(0xffffffffu, ml1, 1));
        ml1 = fmaxf(ml1, __shfl_xor_sync(0xffffffffu, ml1, 2));

        const float mn0 = fmaxf(mx0, ml0);
        const float mn1 = fmaxf(mx1, ml1);
        const float f0 = __expf(mx0 - mn0);
        const float f1 = __expf(mx1 - mn1);
        mx0 = mn0; mx1 = mn1;

        float rs0 = 0.0f, rs1 = 0.0f;
#pragma unroll
        for (int nt = 0; nt < 8; nt++) {
            s[nt][0] = __expf(s[nt][0] - mn0);
            s[nt][1] = __expf(s[nt][1] - mn0);
            s[nt][2] = __expf(s[nt][2] - mn1);
            s[nt][3] = __expf(s[nt][3] - mn1);
            rs0 += s[nt][0] + s[nt][1];
            rs1 += s[nt][2] + s[nt][3];
        }
        rs0 += __shfl_xor_sync(0xffffffffu, rs0, 1);
        rs0 += __shfl_xor_sync(0xffffffffu, rs0, 2);
        rs1 += __shfl_xor_sync(0xffffffffu, rs1, 1);
        rs1 += __shfl_xor_sync(0xffffffffu, rs1, 2);
        l0 = l0 * f0 + rs0;
        l1 = l1 * f1 + rs1;

#pragma unroll
        for (int nt = 0; nt < 16; nt++) {
            o[nt][0] *= f0; o[nt][1] *= f0;
            o[nt][2] *= f1; o[nt][3] *= f1;
        }

#pragma unroll
        for (int nt = 0; nt < 8; nt++) {
            Pw[lr * 36 + nt * 4 + lc]       = pack_h2(s[nt][0], s[nt][1]);
            Pw[(lr + 8) * 36 + nt * 4 + lc] = pack_h2(s[nt][2], s[nt][3]);
        }
        __syncwarp();

#pragma unroll
        for (int ks2 = 0; ks2 < 4; ks2++) {
            uint32_t a[4];
            a[0] = Pw[lr * 36 + ks2 * 8 + lc];
            a[1] = Pw[(lr + 8) * 36 + ks2 * 8 + lc];
            a[2] = Pw[lr * 36 + ks2 * 8 + lc + 4];
            a[3] = Pw[(lr + 8) * 36 + ks2 * 8 + lc + 4];
#pragma unroll
            for (int nt = 0; nt < 16; nt++) {
                uint32_t bf[2];
                *(uint2*)bf = *(const uint2*)&VB[(nt * 4 + ks2) * 64 + lid * 2];
                mma_f16(o[nt], a, bf);
            }
        }

        // prefetch AFTER compute: stage (kb+2)%3 disjoint from laggard readers
        if (kb + 2 < nkb) issueKV(kb + 2, (kb + 2) % 3);
    }

    // ---- epilogue: out-proj A-fragments (g_of). of-tile = b*16 + qb; gm = wid ----
    const float inv0 = 1.0f / l0;
    const float inv1 = 1.0f / l1;
    const int mbp = b * 16 + qb;
    const int gm  = wid;
#pragma unroll
    for (int nt = 0; nt < 16; nt++) {
        const int ch   = h * 2 + (nt >> 3);
        const int ks   = (nt & 7) >> 1;
        const int reg0 = (nt & 1) * 2;
        const size_t base = ((size_t)(mbp * NCH2) + ch) * 4096
                          + (gm * 4 + ks) * 128 + (lr * 4 + lc) * 4 + reg0;
        *(uint2*)&g_of[base] = make_uint2(
            pack_h2(o[nt][0] * inv0, o[nt][1] * inv0),
            pack_h2(o[nt][2] * inv1, o[nt][3] * inv1));
    }
}

// ---------------------------------------------------------------------------
// Launch
// ---------------------------------------------------------------------------
extern "C" void kernel_launch(void* const* d_in, const int* in_sizes, int n_in,
                              void* d_out, int out_size)
{
    const float* x    = (const float*)d_in[0];
    const float* Wqkv = (const float*)d_in[1];
    const float* Wout = (const float*)d_in[2];
    float* out = (float*)d_out;

    cudaFuncSetAttribute((const void*)gemm_qkv,
                         cudaFuncAttributeMaxDynamicSharedMemorySize, QKV_SMEM);
    cudaFuncSetAttribute((const void*)gemm_out,
                         cudaFuncAttributeMaxDynamicSharedMemorySize, OUT_SMEM);
    cudaFuncSetAttribute((const void*)flash_attn_v8,
                         cudaFuncAttributeMaxDynamicSharedMemorySize, ATT_SMEM);

    uint32_t *xf, *of, *wqf, *wof;
    cudaGetSymbolAddress((void**)&xf,  g_xf);
    cudaGetSymbolAddress((void**)&of,  g_of);
    cudaGetSymbolAddress((void**)&wqf, g_wqf);
    cudaGetSymbolAddress((void**)&wof, g_wof);

    // Stage 0: all operand conversions in one launch
    conv_all<<<3072, 256>>>(x, Wqkv, Wout);

    // Stage 1: QKV projection (128x96 tiles, 3-stage ring, 2 CTAs/SM)
    gemm_qkv<<<dim3(64, 32), 128, QKV_SMEM>>>(xf, wqf);

    // Stage 2: flash attention (128-row Q tiles, halved KV traffic)
    flash_attn_v8<<<dim3(16, BATCH * NHEADS), 256, ATT_SMEM>>>();

    // Stage 3: output projection (128x128 tiles, 2 CTAs/SM)
    gemm_out<<<dim3(16, 32), 128, OUT_SMEM>>>(of, wof, out);
}

// round 16
// speedup vs baseline: 1.0835x; 1.0835x over previous
#include <cuda_runtime.h>
#include <cuda_fp16.h>
#include <cstdint>

// Problem constants
#define BATCH   2
#define SEQ     2048
#define DMODEL  2048
#define NHEADS  16
#define DHEAD   128

#define KC2  64                    // K elems per GEMM chunk
#define NCH2 32                    // chunks (K = 2048)
#define SCALE 0.08838834764831845f // 1/sqrt(128)

// ---------------------------------------------------------------------------
// Scratch (alloc-free: __device__ globals)
// ---------------------------------------------------------------------------
__device__ __align__(128) uint32_t g_xf [(size_t)32 * NCH2 * 4096];  // x     [4096,2048]
__device__ __align__(128) uint32_t g_of [(size_t)32 * NCH2 * 4096];  // attn out
__device__ __align__(128) uint32_t g_wqf[(size_t)48 * NCH2 * 4096];  // W_qkv [6144,2048]
__device__ __align__(128) uint32_t g_wof[(size_t)16 * NCH2 * 4096];  // W_out [2048,2048]

__device__ __align__(128) uint32_t g_Qf[(size_t)32 * 32 * 4096];     // pre-scaled by 1/sqrt(dh)
__device__ __align__(128) uint32_t g_Kf[(size_t)32 * 32 * 4096];
__device__ __align__(128) uint32_t g_Vf[(size_t)32 * 32 * 4096];

__device__ __forceinline__ uint32_t pack_h2(float lo, float hi) {
    __half2 h = __floats2half2_rn(lo, hi);
    return *reinterpret_cast<uint32_t*>(&h);
}

__device__ __forceinline__ void mma_f16(float* d, const uint32_t* a, const uint32_t* b) {
    asm volatile(
        "mma.sync.aligned.m16n8k16.row.col.f32.f16.f16.f32 "
        "{%0,%1,%2,%3}, {%4,%5,%6,%7}, {%8,%9}, {%0,%1,%2,%3};"
        : "+f"(d[0]), "+f"(d[1]), "+f"(d[2]), "+f"(d[3])
        : "r"(a[0]), "r"(a[1]), "r"(a[2]), "r"(a[3]), "r"(b[0]), "r"(b[1]));
}

__device__ __forceinline__ void cpa16(uint32_t dst, const void* src) {
    asm volatile("cp.async.cg.shared.global [%0], [%1], 16;"
                 :: "r"(dst), "l"(src) : "memory");
}
#define CPA_COMMIT() asm volatile("cp.async.commit_group;" ::: "memory")
#define CPA_WAIT(n)  asm volatile("cp.async.wait_group %0;" :: "n"(n) : "memory")

__device__ __forceinline__ uint32_t smem_u32(const void* p) {
    uint32_t a;
    asm("{ .reg .u64 t; cvta.to.shared.u64 t, %1; cvt.u32.u64 %0, t; }"
        : "=r"(a) : "l"(p));
    return a;
}

// Fragment index helpers (element (s,d) of head-batch bh)
__device__ __forceinline__ size_t qf_u32(int bh, int s, int d) {
    return (size_t)((bh * 32 + (s >> 6)) * 32 + (d >> 4) * 4 + ((s >> 4) & 3)) * 128
         + (((s & 7) * 4 + ((d & 7) >> 1)) << 2) + (((d >> 3) & 1) << 1) + ((s >> 3) & 1);
}
__device__ __forceinline__ size_t kf_u32(int bh, int s, int d) {
    return (size_t)((bh * 32 + (s >> 6)) * 64 + (d >> 4) * 8 + ((s >> 3) & 7)) * 64
         + (((s & 7) * 4 + ((d & 7) >> 1)) << 1) + ((d >> 3) & 1);
}
__device__ __forceinline__ size_t vf_u16(int bh, int s, int d) {
    return ((size_t)((bh * 32 + (s >> 6)) * 64 + (d >> 3) * 4 + ((s >> 4) & 3)) * 64
         + (((d & 7) * 4 + ((s & 7) >> 1)) << 1) + ((s >> 3) & 1)) * 2 + (s & 1);
}

// ---------------------------------------------------------------------------
// Fused conversion kernel: fp32 row-major -> fp16 fragment layouts.
// ---------------------------------------------------------------------------
__device__ __forceinline__ void conv_A_body(
    const float* __restrict__ src, uint32_t* __restrict__ dst,
    int ch, int mb, int tid, float (*s)[65])
{
    const float* base = src + (size_t)mb * 128 * DMODEL + ch * KC2;
#pragma unroll
    for (int i = 0; i < 8; i++) {
        const int idx = tid + i * 256;
        const int row = idx >> 4, c4 = idx & 15;
        float4 v = *(const float4*)(base + (size_t)row * DMODEL + c4 * 4);
        s[row][c4 * 4 + 0] = v.x; s[row][c4 * 4 + 1] = v.y;
        s[row][c4 * 4 + 2] = v.z; s[row][c4 * 4 + 3] = v.w;
    }
    __syncthreads();
    uint32_t* out = dst + ((size_t)mb * NCH2 + ch) * 4096;
#pragma unroll
    for (int i = 0; i < 16; i++) {
        const int u = tid + i * 256;
        const int blk = u >> 7, rem = u & 127;
        const int lane = rem >> 2, reg = rem & 3;
        const int gm = blk >> 2, ks = blk & 3;
        const int r = (reg & 1) * 8 + (lane >> 2);
        const int c = (reg >> 1) * 8 + (lane & 3) * 2;
        const int k = ks * 16 + c;
        out[u] = pack_h2(s[gm * 16 + r][k], s[gm * 16 + r][k + 1]);
    }
}

__device__ __forceinline__ void conv_B_body(
    const float* __restrict__ src, uint32_t* __restrict__ dst,
    int ch, int nb, int tid, float (*s)[65])
{
    const float* base = src + (size_t)nb * 128 * DMODEL + ch * KC2;
#pragma unroll
    for (int i = 0; i < 8; i++) {
        const int idx = tid + i * 256;
        const int row = idx >> 4, c4 = idx & 15;
        float4 v = *(const float4*)(base + (size_t)row * DMODEL + c4 * 4);
        s[row][c4 * 4 + 0] = v.x; s[row][c4 * 4 + 1] = v.y;
        s[row][c4 * 4 + 2] = v.z; s[row][c4 * 4 + 3] = v.w;
    }
    __syncthreads();
    uint32_t* out = dst + ((size_t)nb * NCH2 + ch) * 4096;
#pragma unroll
    for (int i = 0; i < 16; i++) {
        const int u = tid + i * 256;
        const int blk = u >> 6, rem = u & 63;
        const int lane = rem >> 1, reg = rem & 1;
        const int gn = blk >> 2, ks = blk & 3;
        const int n = lane >> 2, tig = lane & 3;
        const int k = ks * 16 + reg * 8 + tig * 2;
        out[u] = pack_h2(s[gn * 8 + n][k], s[gn * 8 + n][k + 1]);
    }
}

__global__ void __launch_bounds__(256)
conv_all(const float* __restrict__ x, const float* __restrict__ wq,
         const float* __restrict__ wo)
{
    __shared__ float s[128][65];
    const int bid = blockIdx.x;
    const int tid = threadIdx.x;
    if (bid < 1024) {
        conv_A_body(x,  g_xf,  bid & 31, bid >> 5, tid, s);
    } else if (bid < 2560) {
        const int b2 = bid - 1024;
        conv_B_body(wq, g_wqf, b2 & 31, b2 >> 5, tid, s);
    } else {
        const int b2 = bid - 2560;
        conv_B_body(wo, g_wof, b2 & 31, b2 >> 5, tid, s);
    }
}

// ---------------------------------------------------------------------------
// QKV GEMM (round-12): 128-thread CTAs, tile 128x96, 3-stage ring,
// ONE barrier per chunk. Epilogue emits Q/K/V fp16 fragments, Q pre-scaled.
// ---------------------------------------------------------------------------
#define QSTG     7168
#define QKV_SMEM (3 * QSTG * 4)             // 86016 bytes

__global__ void __launch_bounds__(128)
gemm_qkv(const uint32_t* __restrict__ Af, const uint32_t* __restrict__ Bf)
{
    extern __shared__ uint32_t us[];
    const int tid = threadIdx.x;
    const int wid = tid >> 5;
    const int lid = tid & 31;
    const int wm  = wid & 1;
    const int wn  = wid >> 1;
    const int mb  = blockIdx.y;
    const int n0  = blockIdx.x * 96;
    const uint32_t sb = smem_u32(us);

    float acc[4][6][4];
#pragma unroll
    for (int i = 0; i < 4; i++)
#pragma unroll
        for (int j = 0; j < 6; j++)
#pragma unroll
            for (int v = 0; v < 4; v++) acc[i][j][v] = 0.0f;

    auto issue = [&](int c, int st) {
        const uint32_t sA = sb + st * (QSTG * 4);
        const uint32_t sB = sA + 16384;
        const uint32_t* gA = Af + ((size_t)mb * NCH2 + c) * 4096;
#pragma unroll
        for (int i = 0; i < 8; i++) {
            const int o = tid + i * 128;
            cpa16(sA + o * 16, gA + (size_t)o * 4);
        }
#pragma unroll
        for (int i = 0; i < 6; i++) {
            const int idx = tid + i * 128;
            const int g   = idx >> 6;
            const int w64 = idx & 63;
            const int col = n0 + g * 8;
            const uint32_t* gB = Bf + ((size_t)(col >> 7) * NCH2 + c) * 4096
                                    + ((col >> 3) & 15) * 256 + w64 * 4;
            cpa16(sB + (g * 256 + w64 * 4) * 4, gB);
        }
        CPA_COMMIT();
    };

    issue(0, 0);
    issue(1, 1);

    for (int c = 0; c < NCH2; ++c) {
        if (c < NCH2 - 1) { CPA_WAIT(1); }
        else              { CPA_WAIT(0); }
        __syncthreads();

        const uint32_t* uA = us + (c % 3) * QSTG;
        const uint32_t* uB = uA + 4096;
#pragma unroll
        for (int ks = 0; ks < 4; ks++) {
            uint4 a[4];
            uint32_t b[6][2];
#pragma unroll
            for (int mt = 0; mt < 4; mt++)
                a[mt] = *(const uint4*)&uA[(((wm * 4 + mt) * 4 + ks) * 32 + lid) * 4];
#pragma unroll
            for (int nt = 0; nt < 6; nt++) {
                const int g = wn * 6 + nt;
                *(uint2*)b[nt] = *(const uint2*)&uB[g * 256 + ks * 64 + lid * 2];
            }
#pragma unroll
            for (int mt = 0; mt < 4; mt++)
#pragma unroll
                for (int nt = 0; nt < 6; nt++)
                    mma_f16(acc[mt][nt], (const uint32_t*)&a[mt], b[nt]);
        }

        if (c + 2 < NCH2) issue(c + 2, (c + 2) % 3);
    }

    const int lr  = lid >> 2;
    const int lc2 = (lid & 3) * 2;
    const int m0  = mb * 128;
    __half* vh = (__half*)g_Vf;
#pragma unroll
    for (int mt = 0; mt < 4; mt++) {
        const int m = m0 + wm * 64 + mt * 16 + lr;
#pragma unroll
        for (int nt = 0; nt < 6; nt++) {
            const int cg = n0 + wn * 48 + nt * 8 + lc2;
            const int t  = cg >> 11;
            const int h  = (cg >> 7) & (NHEADS - 1);
            const int d  = cg & (DHEAD - 1);
            const int b  = m >> 11;
            const int s  = m & (SEQ - 1);
            const int bh = b * NHEADS + h;
            if (t == 0) {
                g_Qf[qf_u32(bh, s,     d)] = pack_h2(acc[mt][nt][0] * SCALE, acc[mt][nt][1] * SCALE);
                g_Qf[qf_u32(bh, s + 8, d)] = pack_h2(acc[mt][nt][2] * SCALE, acc[mt][nt][3] * SCALE);
            } else if (t == 1) {
                g_Kf[kf_u32(bh, s,     d)] = pack_h2(acc[mt][nt][0], acc[mt][nt][1]);
                g_Kf[kf_u32(bh, s + 8, d)] = pack_h2(acc[mt][nt][2], acc[mt][nt][3]);
            } else {
                vh[vf_u16(bh, s,     d    )] = __float2half_rn(acc[mt][nt][0]);
                vh[vf_u16(bh, s,     d + 1)] = __float2half_rn(acc[mt][nt][1]);
                vh[vf_u16(bh, s + 8, d    )] = __float2half_rn(acc[mt][nt][2]);
                vh[vf_u16(bh, s + 8, d + 1)] = __float2half_rn(acc[mt][nt][3]);
            }
        }
    }
}

// ---------------------------------------------------------------------------
// Output-projection GEMM (round-12): 128 threads, tile 128x128, 3-stage ring
// (96KB -> 2 CTAs/SM), ONE barrier per chunk (issue-after-compute).
// ---------------------------------------------------------------------------
#define OSTG     8192
#define OUT_SMEM (3 * OSTG * 4)             // 98304 bytes

__global__ void __launch_bounds__(128)
gemm_out(const uint32_t* __restrict__ Af, const uint32_t* __restrict__ Bf,
         float* __restrict__ C)
{
    extern __shared__ uint32_t us[];
    const int tid = threadIdx.x;
    const int wid = tid >> 5;
    const int lid = tid & 31;
    const int wm  = wid & 1;
    const int wn  = wid >> 1;
    const int mb  = blockIdx.y;
    const int nb  = blockIdx.x;
    const uint32_t sb = smem_u32(us);

    float acc[4][8][4];
#pragma unroll
    for (int i = 0; i < 4; i++)
#pragma unroll
        for (int j = 0; j < 8; j++)
#pragma unroll
            for (int v = 0; v < 4; v++) acc[i][j][v] = 0.0f;

    auto issue = [&](int c, int st) {
        const uint32_t sA = sb + st * (OSTG * 4);
        const uint32_t sB = sA + 16384;
        const uint32_t* gA = Af + ((size_t)mb * NCH2 + c) * 4096;
        const uint32_t* gB = Bf + ((size_t)nb * NCH2 + c) * 4096;
#pragma unroll
        for (int i = 0; i < 8; i++) {
            const int o = tid + i * 128;
            cpa16(sA + o * 16, gA + (size_t)o * 4);
        }
#pragma unroll
        for (int i = 0; i < 8; i++) {
            const int o = tid + i * 128;
            cpa16(sB + o * 16, gB + (size_t)o * 4);
        }
        CPA_COMMIT();
    };

    issue(0, 0);
    issue(1, 1);

    for (int c = 0; c < NCH2; ++c) {
        if (c < NCH2 - 1) { CPA_WAIT(1); }
        else              { CPA_WAIT(0); }
        __syncthreads();

        const uint32_t* uA = us + (c % 3) * OSTG;
        const uint32_t* uB = uA + 4096;
#pragma unroll
        for (int ks = 0; ks < 4; ks++) {
            uint4 a[4];
            uint32_t b[8][2];
#pragma unroll
            for (int mt = 0; mt < 4; mt++)
                a[mt] = *(const uint4*)&uA[(((wm * 4 + mt) * 4 + ks) * 32 + lid) * 4];
#pragma unroll
            for (int nt = 0; nt < 8; nt++) {
                const int gn = wn * 8 + nt;
                *(uint2*)b[nt] = *(const uint2*)&uB[(gn * 4 + ks) * 64 + lid * 2];
            }
#pragma unroll
            for (int mt = 0; mt < 4; mt++)
#pragma unroll
                for (int nt = 0; nt < 8; nt++)
                    mma_f16(acc[mt][nt], (const uint32_t*)&a[mt], b[nt]);
        }

        if (c + 2 < NCH2) issue(c + 2, (c + 2) % 3);
    }

    const int lr  = lid >> 2;
    const int lc2 = (lid & 3) * 2;
    const int m0  = mb * 128;
    const int n0  = nb * 128;
#pragma unroll
    for (int mt = 0; mt < 4; mt++) {
        const int m = m0 + wm * 64 + mt * 16 + lr;
#pragma unroll
        for (int nt = 0; nt < 8; nt++) {
            const int cg = n0 + wn * 64 + nt * 8 + lc2;
            float* dst = C + (size_t)m * DMODEL + cg;
            *(float2*)dst                         = make_float2(acc[mt][nt][0], acc[mt][nt][1]);
            *(float2*)(dst + (size_t)8 * DMODEL)  = make_float2(acc[mt][nt][2], acc[mt][nt][3]);
        }
    }
}

// ---------------------------------------------------------------------------
// Flash attention v9: 128 threads, 64-row Q tiles, Q (pre-scaled) in regs,
// 3-stage cp.async KV ring, ONE barrier per iteration.
// KEY CHANGE vs v6: P's A-fragments are register repacks of the S C-fragment
// (same lane owns both) — NO smem round-trip, no __syncwarp, 9KB less smem.
// Epilogue writes out-proj A-fragments (g_of) directly.
// ---------------------------------------------------------------------------
#define KV_U32   4096
#define ATT_SMEM (3 * 2 * KV_U32 * 4)       // 98304 bytes (2 CTAs/SM)

__global__ void __launch_bounds__(128)
flash_attn_v9()
{
    extern __shared__ uint32_t sm32[];
    const int tid = threadIdx.x;
    const int wid = tid >> 5;
    const int lid = tid & 31;
    const int qb  = gridDim.x - 1 - blockIdx.x;
    const int bh  = blockIdx.y;
    const int b   = bh >> 4;
    const int h   = bh & (NHEADS - 1);
    const uint32_t sb = smem_u32(sm32);

    uint32_t q[8][4];
    {
        const uint4* qg = (const uint4*)(g_Qf + (size_t)(bh * 32 + qb) * 4096);
#pragma unroll
        for (int kt = 0; kt < 8; kt++) {
            uint4 v = __ldg(&qg[(kt * 4 + wid) * 32 + lid]);
            q[kt][0] = v.x; q[kt][1] = v.y; q[kt][2] = v.z; q[kt][3] = v.w;
        }
    }

    auto issueKV = [&](int kb, int st) {
        const uint4* gk = (const uint4*)(g_Kf + (size_t)(bh * 32 + kb) * KV_U32);
        const uint4* gv = (const uint4*)(g_Vf + (size_t)(bh * 32 + kb) * KV_U32);
        const uint32_t base = sb + st * (2 * KV_U32 * 4);
#pragma unroll
        for (int i = 0; i < 8; i++)
            cpa16(base + (tid + i * 128) * 16, gk + tid + i * 128);
#pragma unroll
        for (int i = 0; i < 8; i++)
            cpa16(base + KV_U32 * 4 + (tid + i * 128) * 16, gv + tid + i * 128);
        CPA_COMMIT();
    };

    float o[16][4];
#pragma unroll
    for (int nt = 0; nt < 16; nt++)
#pragma unroll
        for (int v = 0; v < 4; v++) o[nt][v] = 0.0f;

    float mx0 = -1e30f, mx1 = -1e30f, l0 = 0.0f, l1 = 0.0f;
    const int lr = lid >> 2;
    const int lc = lid & 3;
    const int q0 = qb * 64;
    const int row0 = q0 + wid * 16 + lr;
    const int row1 = row0 + 8;

    issueKV(0, 0);
    if (qb >= 1) issueKV(1, 1);

    for (int kb = 0; kb <= qb; kb++) {
        if (kb < qb) { CPA_WAIT(1); }
        else         { CPA_WAIT(0); }
        __syncthreads();

        const uint32_t* KB = sm32 + (kb % 3) * 2 * KV_U32;
        const uint32_t* VB = KB + KV_U32;

        float s[8][4];
#pragma unroll
        for (int nt = 0; nt < 8; nt++)
#pragma unroll
            for (int v = 0; v < 4; v++) s[nt][v] = 0.0f;

#pragma unroll
        for (int kt = 0; kt < 8; kt++)
#pragma unroll
            for (int nt = 0; nt < 8; nt++) {
                uint32_t bf[2];
                *(uint2*)bf = *(const uint2*)&KB[(kt * 8 + nt) * 64 + lid * 2];
                mma_f16(s[nt], q[kt], bf);
            }

        // Q pre-scaled; mask diagonal block only
        const bool domask = (kb == qb);
        const int k0 = kb * 64;
        float ml0 = -1e30f, ml1 = -1e30f;
#pragma unroll
        for (int nt = 0; nt < 8; nt++) {
            const int c0 = k0 + nt * 8 + lc * 2;
            if (domask) {
                if (c0     > row0) s[nt][0] = -1e30f;
                if (c0 + 1 > row0) s[nt][1] = -1e30f;
                if (c0     > row1) s[nt][2] = -1e30f;
                if (c0 + 1 > row1) s[nt][3] = -1e30f;
            }
            ml0 = fmaxf(ml0, fmaxf(s[nt][0], s[nt][1]));
            ml1 = fmaxf(ml1, fmaxf(s[nt][2], s[nt][3]));
        }
        ml0 = fmaxf(ml0, __shfl_xor_sync(0xffffffffu, ml0, 1));
        ml0 = fmaxf(ml0, __shfl_xor_sync(0xffffffffu, ml0, 2));
        ml1 = fmaxf(ml1, __shfl_xor_sync(0xffffffffu, ml1, 1));
        ml1 = fmaxf(ml1, __shfl_xor_sync(0xffffffffu, ml1, 2));

        const float mn0 = fmaxf(mx0, ml0);
        const float mn1 = fmaxf(mx1, ml1);
        const float f0 = __expf(mx0 - mn0);
        const float f1 = __expf(mx1 - mn1);
        mx0 = mn0; mx1 = mn1;

        float rs0 = 0.0f, rs1 = 0.0f;
        uint32_t p[8][2];                      // P in A-frag register form
#pragma unroll
        for (int nt = 0; nt < 8; nt++) {
            s[nt][0] = __expf(s[nt][0] - mn0);
            s[nt][1] = __expf(s[nt][1] - mn0);
            s[nt][2] = __expf(s[nt][2] - mn1);
            s[nt][3] = __expf(s[nt][3] - mn1);
            rs0 += s[nt][0] + s[nt][1];
            rs1 += s[nt][2] + s[nt][3];
            p[nt][0] = pack_h2(s[nt][0], s[nt][1]);   // rows lr,   k pair
            p[nt][1] = pack_h2(s[nt][2], s[nt][3]);   // rows lr+8, k pair
        }
        rs0 += __shfl_xor_sync(0xffffffffu, rs0, 1);
        rs0 += __shfl_xor_sync(0xffffffffu, rs0, 2);
        rs1 += __shfl_xor_sync(0xffffffffu, rs1, 1);
        rs1 += __shfl_xor_sync(0xffffffffu, rs1, 2);
        l0 = l0 * f0 + rs0;
        l1 = l1 * f1 + rs1;

#pragma unroll
        for (int nt = 0; nt < 16; nt++) {
            o[nt][0] *= f0; o[nt][1] *= f0;
            o[nt][2] *= f1; o[nt][3] *= f1;
        }

        // ---- O += P . V : A-fragments straight from registers ----
#pragma unroll
        for (int ks2 = 0; ks2 < 4; ks2++) {
            uint32_t a[4];
            a[0] = p[2 * ks2][0];              // rows 0-7,  k 0-7 of chunk
            a[1] = p[2 * ks2][1];              // rows 8-15, k 0-7
            a[2] = p[2 * ks2 + 1][0];          // rows 0-7,  k 8-15
            a[3] = p[2 * ks2 + 1][1];          // rows 8-15, k 8-15
#pragma unroll
            for (int nt = 0; nt < 16; nt++) {
                uint32_t bf[2];
                *(uint2*)bf = *(const uint2*)&VB[(nt * 4 + ks2) * 64 + lid * 2];
                mma_f16(o[nt], a, bf);
            }
        }

        if (kb + 2 <= qb) issueKV(kb + 2, (kb + 2) % 3);
    }

    const float inv0 = 1.0f / l0;
    const float inv1 = 1.0f / l1;
    const int mbp = b * 16 + (qb >> 1);
    const int gm  = (qb & 1) * 4 + wid;
#pragma unroll
    for (int nt = 0; nt < 16; nt++) {
        const int ch   = h * 2 + (nt >> 3);
        const int ks   = (nt & 7) >> 1;
        const int reg0 = (nt & 1) * 2;
        const size_t base = ((size_t)(mbp * NCH2) + ch) * 4096
                          + (gm * 4 + ks) * 128 + (lr * 4 + lc) * 4 + reg0;
        *(uint2*)&g_of[base] = make_uint2(
            pack_h2(o[nt][0] * inv0, o[nt][1] * inv0),
            pack_h2(o[nt][2] * inv1, o[nt][3] * inv1));
    }
}

// ---------------------------------------------------------------------------
// Launch
// ---------------------------------------------------------------------------
extern "C" void kernel_launch(void* const* d_in, const int* in_sizes, int n_in,
                              void* d_out, int out_size)
{
    const float* x    = (const float*)d_in[0];
    const float* Wqkv = (const float*)d_in[1];
    const float* Wout = (const float*)d_in[2];
    float* out = (float*)d_out;

    cudaFuncSetAttribute((const void*)gemm_qkv,
                         cudaFuncAttributeMaxDynamicSharedMemorySize, QKV_SMEM);
    cudaFuncSetAttribute((const void*)gemm_out,
                         cudaFuncAttributeMaxDynamicSharedMemorySize, OUT_SMEM);
    cudaFuncSetAttribute((const void*)flash_attn_v9,
                         cudaFuncAttributeMaxDynamicSharedMemorySize, ATT_SMEM);

    uint32_t *xf, *of, *wqf, *wof;
    cudaGetSymbolAddress((void**)&xf,  g_xf);
    cudaGetSymbolAddress((void**)&of,  g_of);
    cudaGetSymbolAddress((void**)&wqf, g_wqf);
    cudaGetSymbolAddress((void**)&wof, g_wof);

    // Stage 0: all operand conversions in one launch
    conv_all<<<3072, 256>>>(x, Wqkv, Wout);

    // Stage 1: QKV projection (128x96 tiles, 3-stage ring, 2 CTAs/SM)
    gemm_qkv<<<dim3(64, 32), 128, QKV_SMEM>>>(xf, wqf);

    // Stage 2: flash attention (register-direct PV, no P smem round-trip)
    flash_attn_v9<<<dim3(32, BATCH * NHEADS), 128, ATT_SMEM>>>();

    // Stage 3: output projection (128x128 tiles, 2 CTAs/SM)
    gemm_out<<<dim3(16, 32), 128, OUT_SMEM>>>(of, wof, out);
}

// round 17
// speedup vs baseline: 1.0998x; 1.0150x over previous
#include <cuda_runtime.h>
#include <cuda_fp16.h>
#include <cstdint>

// Problem constants
#define BATCH   2
#define SEQ     2048
#define DMODEL  2048
#define NHEADS  16
#define DHEAD   128

#define KC2  64                    // K elems per GEMM chunk
#define NCH2 32                    // chunks (K = 2048)
#define SCALE 0.08838834764831845f // 1/sqrt(128)

// ---------------------------------------------------------------------------
// Scratch (alloc-free: __device__ globals)
// ---------------------------------------------------------------------------
__device__ __align__(128) uint32_t g_xf [(size_t)32 * NCH2 * 4096];  // x     [4096,2048]
__device__ __align__(128) uint32_t g_of [(size_t)32 * NCH2 * 4096];  // attn out
__device__ __align__(128) uint32_t g_wqf[(size_t)48 * NCH2 * 4096];  // W_qkv [6144,2048]
__device__ __align__(128) uint32_t g_wof[(size_t)16 * NCH2 * 4096];  // W_out [2048,2048]

__device__ __align__(128) uint32_t g_Qf[(size_t)32 * 32 * 4096];     // pre-scaled by 1/sqrt(dh)
__device__ __align__(128) uint32_t g_Kf[(size_t)32 * 32 * 4096];
__device__ __align__(128) uint32_t g_Vf[(size_t)32 * 32 * 4096];

__device__ __forceinline__ uint32_t pack_h2(float lo, float hi) {
    __half2 h = __floats2half2_rn(lo, hi);
    return *reinterpret_cast<uint32_t*>(&h);
}

__device__ __forceinline__ void mma_f16(float* d, const uint32_t* a, const uint32_t* b) {
    asm volatile(
        "mma.sync.aligned.m16n8k16.row.col.f32.f16.f16.f32 "
        "{%0,%1,%2,%3}, {%4,%5,%6,%7}, {%8,%9}, {%0,%1,%2,%3};"
        : "+f"(d[0]), "+f"(d[1]), "+f"(d[2]), "+f"(d[3])
        : "r"(a[0]), "r"(a[1]), "r"(a[2]), "r"(a[3]), "r"(b[0]), "r"(b[1]));
}

__device__ __forceinline__ void cpa16(uint32_t dst, const void* src) {
    asm volatile("cp.async.cg.shared.global [%0], [%1], 16;"
                 :: "r"(dst), "l"(src) : "memory");
}
#define CPA_COMMIT() asm volatile("cp.async.commit_group;" ::: "memory")
#define CPA_WAIT(n)  asm volatile("cp.async.wait_group %0;" :: "n"(n) : "memory")

__device__ __forceinline__ uint32_t smem_u32(const void* p) {
    uint32_t a;
    asm("{ .reg .u64 t; cvta.to.shared.u64 t, %1; cvt.u32.u64 %0, t; }"
        : "=r"(a) : "l"(p));
    return a;
}

// Fragment index helpers (element (s,d) of head-batch bh)
__device__ __forceinline__ size_t qf_u32(int bh, int s, int d) {
    return (size_t)((bh * 32 + (s >> 6)) * 32 + (d >> 4) * 4 + ((s >> 4) & 3)) * 128
         + (((s & 7) * 4 + ((d & 7) >> 1)) << 2) + (((d >> 3) & 1) << 1) + ((s >> 3) & 1);
}
__device__ __forceinline__ size_t kf_u32(int bh, int s, int d) {
    return (size_t)((bh * 32 + (s >> 6)) * 64 + (d >> 4) * 8 + ((s >> 3) & 7)) * 64
         + (((s & 7) * 4 + ((d & 7) >> 1)) << 1) + ((d >> 3) & 1);
}
__device__ __forceinline__ size_t vf_u16(int bh, int s, int d) {
    return ((size_t)((bh * 32 + (s >> 6)) * 64 + (d >> 3) * 4 + ((s >> 4) & 3)) * 64
         + (((d & 7) * 4 + ((s & 7) >> 1)) << 1) + ((s >> 3) & 1)) * 2 + (s & 1);
}

// ---------------------------------------------------------------------------
// Fused conversion kernel: fp32 row-major -> fp16 fragment layouts.
// ---------------------------------------------------------------------------
__device__ __forceinline__ void conv_A_body(
    const float* __restrict__ src, uint32_t* __restrict__ dst,
    int ch, int mb, int tid, float (*s)[65])
{
    const float* base = src + (size_t)mb * 128 * DMODEL + ch * KC2;
#pragma unroll
    for (int i = 0; i < 8; i++) {
        const int idx = tid + i * 256;
        const int row = idx >> 4, c4 = idx & 15;
        float4 v = *(const float4*)(base + (size_t)row * DMODEL + c4 * 4);
        s[row][c4 * 4 + 0] = v.x; s[row][c4 * 4 + 1] = v.y;
        s[row][c4 * 4 + 2] = v.z; s[row][c4 * 4 + 3] = v.w;
    }
    __syncthreads();
    uint32_t* out = dst + ((size_t)mb * NCH2 + ch) * 4096;
#pragma unroll
    for (int i = 0; i < 16; i++) {
        const int u = tid + i * 256;
        const int blk = u >> 7, rem = u & 127;
        const int lane = rem >> 2, reg = rem & 3;
        const int gm = blk >> 2, ks = blk & 3;
        const int r = (reg & 1) * 8 + (lane >> 2);
        const int c = (reg >> 1) * 8 + (lane & 3) * 2;
        const int k = ks * 16 + c;
        out[u] = pack_h2(s[gm * 16 + r][k], s[gm * 16 + r][k + 1]);
    }
}

__device__ __forceinline__ void conv_B_body(
    const float* __restrict__ src, uint32_t* __restrict__ dst,
    int ch, int nb, int tid, float (*s)[65])
{
    const float* base = src + (size_t)nb * 128 * DMODEL + ch * KC2;
#pragma unroll
    for (int i = 0; i < 8; i++) {
        const int idx = tid + i * 256;
        const int row = idx >> 4, c4 = idx & 15;
        float4 v = *(const float4*)(base + (size_t)row * DMODEL + c4 * 4);
        s[row][c4 * 4 + 0] = v.x; s[row][c4 * 4 + 1] = v.y;
        s[row][c4 * 4 + 2] = v.z; s[row][c4 * 4 + 3] = v.w;
    }
    __syncthreads();
    uint32_t* out = dst + ((size_t)nb * NCH2 + ch) * 4096;
#pragma unroll
    for (int i = 0; i < 16; i++) {
        const int u = tid + i * 256;
        const int blk = u >> 6, rem = u & 63;
        const int lane = rem >> 1, reg = rem & 1;
        const int gn = blk >> 2, ks = blk & 3;
        const int n = lane >> 2, tig = lane & 3;
        const int k = ks * 16 + reg * 8 + tig * 2;
        out[u] = pack_h2(s[gn * 8 + n][k], s[gn * 8 + n][k + 1]);
    }
}

__global__ void __launch_bounds__(256)
conv_all(const float* __restrict__ x, const float* __restrict__ wq,
         const float* __restrict__ wo)
{
    __shared__ float s[128][65];
    const int bid = blockIdx.x;
    const int tid = threadIdx.x;
    if (bid < 1024) {
        conv_A_body(x,  g_xf,  bid & 31, bid >> 5, tid, s);
    } else if (bid < 2560) {
        const int b2 = bid - 1024;
        conv_B_body(wq, g_wqf, b2 & 31, b2 >> 5, tid, s);
    } else {
        const int b2 = bid - 2560;
        conv_B_body(wo, g_wof, b2 & 31, b2 >> 5, tid, s);
    }
}

// ---------------------------------------------------------------------------
// QKV GEMM: 128-thread CTAs, tile 128x96, 3-stage ring, ONE barrier per
// chunk. Prefetch for c+2 issued EARLY (after the first ks group) — safe:
// post-barrier-c every warp is in iter c, so writes to stage (c+2)%3 never
// collide with reads of stage c%3. Epilogue: Q/K/V fragments, Q pre-scaled.
// ---------------------------------------------------------------------------
#define QSTG     7168
#define QKV_SMEM (3 * QSTG * 4)             // 86016 bytes

__global__ void __launch_bounds__(128)
gemm_qkv(const uint32_t* __restrict__ Af, const uint32_t* __restrict__ Bf)
{
    extern __shared__ uint32_t us[];
    const int tid = threadIdx.x;
    const int wid = tid >> 5;
    const int lid = tid & 31;
    const int wm  = wid & 1;
    const int wn  = wid >> 1;
    const int mb  = blockIdx.y;
    const int n0  = blockIdx.x * 96;
    const uint32_t sb = smem_u32(us);

    float acc[4][6][4];
#pragma unroll
    for (int i = 0; i < 4; i++)
#pragma unroll
        for (int j = 0; j < 6; j++)
#pragma unroll
            for (int v = 0; v < 4; v++) acc[i][j][v] = 0.0f;

    auto issue = [&](int c, int st) {
        const uint32_t sA = sb + st * (QSTG * 4);
        const uint32_t sB = sA + 16384;
        const uint32_t* gA = Af + ((size_t)mb * NCH2 + c) * 4096;
#pragma unroll
        for (int i = 0; i < 8; i++) {
            const int o = tid + i * 128;
            cpa16(sA + o * 16, gA + (size_t)o * 4);
        }
#pragma unroll
        for (int i = 0; i < 6; i++) {
            const int idx = tid + i * 128;
            const int g   = idx >> 6;
            const int w64 = idx & 63;
            const int col = n0 + g * 8;
            const uint32_t* gB = Bf + ((size_t)(col >> 7) * NCH2 + c) * 4096
                                    + ((col >> 3) & 15) * 256 + w64 * 4;
            cpa16(sB + (g * 256 + w64 * 4) * 4, gB);
        }
        CPA_COMMIT();
    };

    auto compute_ks = [&](const uint32_t* uA, const uint32_t* uB, int ks) {
        uint4 a[4];
        uint32_t b[6][2];
#pragma unroll
        for (int mt = 0; mt < 4; mt++)
            a[mt] = *(const uint4*)&uA[(((wm * 4 + mt) * 4 + ks) * 32 + lid) * 4];
#pragma unroll
        for (int nt = 0; nt < 6; nt++) {
            const int g = wn * 6 + nt;
            *(uint2*)b[nt] = *(const uint2*)&uB[g * 256 + ks * 64 + lid * 2];
        }
#pragma unroll
        for (int mt = 0; mt < 4; mt++)
#pragma unroll
            for (int nt = 0; nt < 6; nt++)
                mma_f16(acc[mt][nt], (const uint32_t*)&a[mt], b[nt]);
    };

    issue(0, 0);
    issue(1, 1);

    for (int c = 0; c < NCH2; ++c) {
        if (c < NCH2 - 1) { CPA_WAIT(1); }
        else              { CPA_WAIT(0); }
        __syncthreads();

        const uint32_t* uA = us + (c % 3) * QSTG;
        const uint32_t* uB = uA + 4096;

        compute_ks(uA, uB, 0);
        if (c + 2 < NCH2) issue(c + 2, (c + 2) % 3);   // early prefetch
        compute_ks(uA, uB, 1);
        compute_ks(uA, uB, 2);
        compute_ks(uA, uB, 3);
    }

    const int lr  = lid >> 2;
    const int lc2 = (lid & 3) * 2;
    const int m0  = mb * 128;
    __half* vh = (__half*)g_Vf;
#pragma unroll
    for (int mt = 0; mt < 4; mt++) {
        const int m = m0 + wm * 64 + mt * 16 + lr;
#pragma unroll
        for (int nt = 0; nt < 6; nt++) {
            const int cg = n0 + wn * 48 + nt * 8 + lc2;
            const int t  = cg >> 11;
            const int h  = (cg >> 7) & (NHEADS - 1);
            const int d  = cg & (DHEAD - 1);
            const int b  = m >> 11;
            const int s  = m & (SEQ - 1);
            const int bh = b * NHEADS + h;
            if (t == 0) {
                g_Qf[qf_u32(bh, s,     d)] = pack_h2(acc[mt][nt][0] * SCALE, acc[mt][nt][1] * SCALE);
                g_Qf[qf_u32(bh, s + 8, d)] = pack_h2(acc[mt][nt][2] * SCALE, acc[mt][nt][3] * SCALE);
            } else if (t == 1) {
                g_Kf[kf_u32(bh, s,     d)] = pack_h2(acc[mt][nt][0], acc[mt][nt][1]);
                g_Kf[kf_u32(bh, s + 8, d)] = pack_h2(acc[mt][nt][2], acc[mt][nt][3]);
            } else {
                vh[vf_u16(bh, s,     d    )] = __float2half_rn(acc[mt][nt][0]);
                vh[vf_u16(bh, s,     d + 1)] = __float2half_rn(acc[mt][nt][1]);
                vh[vf_u16(bh, s + 8, d    )] = __float2half_rn(acc[mt][nt][2]);
                vh[vf_u16(bh, s + 8, d + 1)] = __float2half_rn(acc[mt][nt][3]);
            }
        }
    }
}

// ---------------------------------------------------------------------------
// Output-projection GEMM: 128 threads, tile 128x128, 3-stage ring
// (96KB -> 2 CTAs/SM), ONE barrier per chunk, EARLY prefetch issue.
// ---------------------------------------------------------------------------
#define OSTG     8192
#define OUT_SMEM (3 * OSTG * 4)             // 98304 bytes

__global__ void __launch_bounds__(128)
gemm_out(const uint32_t* __restrict__ Af, const uint32_t* __restrict__ Bf,
         float* __restrict__ C)
{
    extern __shared__ uint32_t us[];
    const int tid = threadIdx.x;
    const int wid = tid >> 5;
    const int lid = tid & 31;
    const int wm  = wid & 1;
    const int wn  = wid >> 1;
    const int mb  = blockIdx.y;
    const int nb  = blockIdx.x;
    const uint32_t sb = smem_u32(us);

    float acc[4][8][4];
#pragma unroll
    for (int i = 0; i < 4; i++)
#pragma unroll
        for (int j = 0; j < 8; j++)
#pragma unroll
            for (int v = 0; v < 4; v++) acc[i][j][v] = 0.0f;

    auto issue = [&](int c, int st) {
        const uint32_t sA = sb + st * (OSTG * 4);
        const uint32_t sB = sA + 16384;
        const uint32_t* gA = Af + ((size_t)mb * NCH2 + c) * 4096;
        const uint32_t* gB = Bf + ((size_t)nb * NCH2 + c) * 4096;
#pragma unroll
        for (int i = 0; i < 8; i++) {
            const int o = tid + i * 128;
            cpa16(sA + o * 16, gA + (size_t)o * 4);
        }
#pragma unroll
        for (int i = 0; i < 8; i++) {
            const int o = tid + i * 128;
            cpa16(sB + o * 16, gB + (size_t)o * 4);
        }
        CPA_COMMIT();
    };

    auto compute_ks = [&](const uint32_t* uA, const uint32_t* uB, int ks) {
        uint4 a[4];
        uint32_t b[8][2];
#pragma unroll
        for (int mt = 0; mt < 4; mt++)
            a[mt] = *(const uint4*)&uA[(((wm * 4 + mt) * 4 + ks) * 32 + lid) * 4];
#pragma unroll
        for (int nt = 0; nt < 8; nt++) {
            const int gn = wn * 8 + nt;
            *(uint2*)b[nt] = *(const uint2*)&uB[(gn * 4 + ks) * 64 + lid * 2];
        }
#pragma unroll
        for (int mt = 0; mt < 4; mt++)
#pragma unroll
            for (int nt = 0; nt < 8; nt++)
                mma_f16(acc[mt][nt], (const uint32_t*)&a[mt], b[nt]);
    };

    issue(0, 0);
    issue(1, 1);

    for (int c = 0; c < NCH2; ++c) {
        if (c < NCH2 - 1) { CPA_WAIT(1); }
        else              { CPA_WAIT(0); }
        __syncthreads();

        const uint32_t* uA = us + (c % 3) * OSTG;
        const uint32_t* uB = uA + 4096;

        compute_ks(uA, uB, 0);
        if (c + 2 < NCH2) issue(c + 2, (c + 2) % 3);   // early prefetch
        compute_ks(uA, uB, 1);
        compute_ks(uA, uB, 2);
        compute_ks(uA, uB, 3);
    }

    const int lr  = lid >> 2;
    const int lc2 = (lid & 3) * 2;
    const int m0  = mb * 128;
    const int n0  = nb * 128;
#pragma unroll
    for (int mt = 0; mt < 4; mt++) {
        const int m = m0 + wm * 64 + mt * 16 + lr;
#pragma unroll
        for (int nt = 0; nt < 8; nt++) {
            const int cg = n0 + wn * 64 + nt * 8 + lc2;
            float* dst = C + (size_t)m * DMODEL + cg;
            *(float2*)dst                         = make_float2(acc[mt][nt][0], acc[mt][nt][1]);
            *(float2*)(dst + (size_t)8 * DMODEL)  = make_float2(acc[mt][nt][2], acc[mt][nt][3]);
        }
    }
}

// ---------------------------------------------------------------------------
// Flash attention v9b: 128 threads, 64-row Q tiles, Q (pre-scaled) in regs,
// 3-stage cp.async KV ring, ONE barrier per iteration, register-direct PV.
// KV prefetch for kb+2 issued EARLY (right after the QK MMAs).
// Epilogue writes out-proj A-fragments (g_of) directly.
// ---------------------------------------------------------------------------
#define KV_U32   4096
#define ATT_SMEM (3 * 2 * KV_U32 * 4)       // 98304 bytes (2 CTAs/SM)

__global__ void __launch_bounds__(128)
flash_attn_v9()
{
    extern __shared__ uint32_t sm32[];
    const int tid = threadIdx.x;
    const int wid = tid >> 5;
    const int lid = tid & 31;
    const int qb  = gridDim.x - 1 - blockIdx.x;
    const int bh  = blockIdx.y;
    const int b   = bh >> 4;
    const int h   = bh & (NHEADS - 1);
    const uint32_t sb = smem_u32(sm32);

    uint32_t q[8][4];
    {
        const uint4* qg = (const uint4*)(g_Qf + (size_t)(bh * 32 + qb) * 4096);
#pragma unroll
        for (int kt = 0; kt < 8; kt++) {
            uint4 v = __ldg(&qg[(kt * 4 + wid) * 32 + lid]);
            q[kt][0] = v.x; q[kt][1] = v.y; q[kt][2] = v.z; q[kt][3] = v.w;
        }
    }

    auto issueKV = [&](int kb, int st) {
        const uint4* gk = (const uint4*)(g_Kf + (size_t)(bh * 32 + kb) * KV_U32);
        const uint4* gv = (const uint4*)(g_Vf + (size_t)(bh * 32 + kb) * KV_U32);
        const uint32_t base = sb + st * (2 * KV_U32 * 4);
#pragma unroll
        for (int i = 0; i < 8; i++)
            cpa16(base + (tid + i * 128) * 16, gk + tid + i * 128);
#pragma unroll
        for (int i = 0; i < 8; i++)
            cpa16(base + KV_U32 * 4 + (tid + i * 128) * 16, gv + tid + i * 128);
        CPA_COMMIT();
    };

    float o[16][4];
#pragma unroll
    for (int nt = 0; nt < 16; nt++)
#pragma unroll
        for (int v = 0; v < 4; v++) o[nt][v] = 0.0f;

    float mx0 = -1e30f, mx1 = -1e30f, l0 = 0.0f, l1 = 0.0f;
    const int lr = lid >> 2;
    const int lc = lid & 3;
    const int q0 = qb * 64;
    const int row0 = q0 + wid * 16 + lr;
    const int row1 = row0 + 8;

    issueKV(0, 0);
    if (qb >= 1) issueKV(1, 1);

    for (int kb = 0; kb <= qb; kb++) {
        if (kb < qb) { CPA_WAIT(1); }
        else         { CPA_WAIT(0); }
        __syncthreads();

        const uint32_t* KB = sm32 + (kb % 3) * 2 * KV_U32;
        const uint32_t* VB = KB + KV_U32;

        float s[8][4];
#pragma unroll
        for (int nt = 0; nt < 8; nt++)
#pragma unroll
            for (int v = 0; v < 4; v++) s[nt][v] = 0.0f;

#pragma unroll
        for (int kt = 0; kt < 8; kt++)
#pragma unroll
            for (int nt = 0; nt < 8; nt++) {
                uint32_t bf[2];
                *(uint2*)bf = *(const uint2*)&KB[(kt * 8 + nt) * 64 + lid * 2];
                mma_f16(s[nt], q[kt], bf);
            }

        // early KV prefetch: stage (kb+2)%3 disjoint from stage kb%3 readers
        if (kb + 2 <= qb) issueKV(kb + 2, (kb + 2) % 3);

        // Q pre-scaled; mask diagonal block only
        const bool domask = (kb == qb);
        const int k0 = kb * 64;
        float ml0 = -1e30f, ml1 = -1e30f;
#pragma unroll
        for (int nt = 0; nt < 8; nt++) {
            const int c0 = k0 + nt * 8 + lc * 2;
            if (domask) {
                if (c0     > row0) s[nt][0] = -1e30f;
                if (c0 + 1 > row0) s[nt][1] = -1e30f;
                if (c0     > row1) s[nt][2] = -1e30f;
                if (c0 + 1 > row1) s[nt][3] = -1e30f;
            }
            ml0 = fmaxf(ml0, fmaxf(s[nt][0], s[nt][1]));
            ml1 = fmaxf(ml1, fmaxf(s[nt][2], s[nt][3]));
        }
        ml0 = fmaxf(ml0, __shfl_xor_sync(0xffffffffu, ml0, 1));
        ml0 = fmaxf(ml0, __shfl_xor_sync(0xffffffffu, ml0, 2));
        ml1 = fmaxf(ml1, __shfl_xor_sync(0xffffffffu, ml1, 1));
        ml1 = fmaxf(ml1, __shfl_xor_sync(0xffffffffu, ml1, 2));

        const float mn0 = fmaxf(mx0, ml0);
        const float mn1 = fmaxf(mx1, ml1);
        const float f0 = __expf(mx0 - mn0);
        const float f1 = __expf(mx1 - mn1);
        mx0 = mn0; mx1 = mn1;

        float rs0 = 0.0f, rs1 = 0.0f;
        uint32_t p[8][2];                      // P in A-frag register form
#pragma unroll
        for (int nt = 0; nt < 8; nt++) {
            s[nt][0] = __expf(s[nt][0] - mn0);
            s[nt][1] = __expf(s[nt][1] - mn0);
            s[nt][2] = __expf(s[nt][2] - mn1);
            s[nt][3] = __expf(s[nt][3] - mn1);
            rs0 += s[nt][0] + s[nt][1];
            rs1 += s[nt][2] + s[nt][3];
            p[nt][0] = pack_h2(s[nt][0], s[nt][1]);
            p[nt][1] = pack_h2(s[nt][2], s[nt][3]);
        }
        rs0 += __shfl_xor_sync(0xffffffffu, rs0, 1);
        rs0 += __shfl_xor_sync(0xffffffffu, rs0, 2);
        rs1 += __shfl_xor_sync(0xffffffffu, rs1, 1);
        rs1 += __shfl_xor_sync(0xffffffffu, rs1, 2);
        l0 = l0 * f0 + rs0;
        l1 = l1 * f1 + rs1;

#pragma unroll
        for (int nt = 0; nt < 16; nt++) {
            o[nt][0] *= f0; o[nt][1] *= f0;
            o[nt][2] *= f1; o[nt][3] *= f1;
        }

        // ---- O += P . V : A-fragments straight from registers ----
#pragma unroll
        for (int ks2 = 0; ks2 < 4; ks2++) {
            uint32_t a[4];
            a[0] = p[2 * ks2][0];
            a[1] = p[2 * ks2][1];
            a[2] = p[2 * ks2 + 1][0];
            a[3] = p[2 * ks2 + 1][1];
#pragma unroll
            for (int nt = 0; nt < 16; nt++) {
                uint32_t bf[2];
                *(uint2*)bf = *(const uint2*)&VB[(nt * 4 + ks2) * 64 + lid * 2];
                mma_f16(o[nt], a, bf);
            }
        }
    }

    const float inv0 = 1.0f / l0;
    const float inv1 = 1.0f / l1;
    const int mbp = b * 16 + (qb >> 1);
    const int gm  = (qb & 1) * 4 + wid;
#pragma unroll
    for (int nt = 0; nt < 16; nt++) {
        const int ch   = h * 2 + (nt >> 3);
        const int ks   = (nt & 7) >> 1;
        const int reg0 = (nt & 1) * 2;
        const size_t base = ((size_t)(mbp * NCH2) + ch) * 4096
                          + (gm * 4 + ks) * 128 + (lr * 4 + lc) * 4 + reg0;
        *(uint2*)&g_of[base] = make_uint2(
            pack_h2(o[nt][0] * inv0, o[nt][1] * inv0),
            pack_h2(o[nt][2] * inv1, o[nt][3] * inv1));
    }
}

// ---------------------------------------------------------------------------
// Launch
// ---------------------------------------------------------------------------
extern "C" void kernel_launch(void* const* d_in, const int* in_sizes, int n_in,
                              void* d_out, int out_size)
{
    const float* x    = (const float*)d_in[0];
    const float* Wqkv = (const float*)d_in[1];
    const float* Wout = (const float*)d_in[2];
    float* out = (float*)d_out;

    cudaFuncSetAttribute((const void*)gemm_qkv,
                         cudaFuncAttributeMaxDynamicSharedMemorySize, QKV_SMEM);
    cudaFuncSetAttribute((const void*)gemm_out,
                         cudaFuncAttributeMaxDynamicSharedMemorySize, OUT_SMEM);
    cudaFuncSetAttribute((const void*)flash_attn_v9,
                         cudaFuncAttributeMaxDynamicSharedMemorySize, ATT_SMEM);

    uint32_t *xf, *of, *wqf, *wof;
    cudaGetSymbolAddress((void**)&xf,  g_xf);
    cudaGetSymbolAddress((void**)&of,  g_of);
    cudaGetSymbolAddress((void**)&wqf, g_wqf);
    cudaGetSymbolAddress((void**)&wof, g_wof);

    // Stage 0: all operand conversions in one launch
    conv_all<<<3072, 256>>>(x, Wqkv, Wout);

    // Stage 1: QKV projection (128x96 tiles, 3-stage ring, early prefetch)
    gemm_qkv<<<dim3(64, 32), 128, QKV_SMEM>>>(xf, wqf);

    // Stage 2: flash attention (register-direct PV, early KV prefetch)
    flash_attn_v9<<<dim3(32, BATCH * NHEADS), 128, ATT_SMEM>>>();

    // Stage 3: output projection (128x128 tiles, early prefetch)
    gemm_out<<<dim3(16, 32), 128, OUT_SMEM>>>(of, wof, out);
}